// round 1
// baseline (speedup 1.0000x reference)
#include <cuda_runtime.h>
#include <cuda_bf16.h>
#include <math.h>

#define N_NODES 100000
#define N_EDGES 3200000
#define FEAT 256
#define FEAT4 (FEAT / 4)

// ---------------- device scratch (allocation-free contract) ----------------
__device__ int   g_deg_out[N_NODES];
__device__ int   g_deg_in[N_NODES];
__device__ float g_rs_out[N_NODES];   // rsqrt(max(deg_out,1))
__device__ float g_rs_in[N_NODES];    // rsqrt(max(deg_in,1))

// vectorized f32 reduction to global memory (sm_90+; PTX ISA 8.1)
__device__ __forceinline__ void red_add_v4(float4* addr, float4 v) {
    asm volatile("red.global.add.v4.f32 [%0], {%1, %2, %3, %4};"
                 :: "l"(addr), "f"(v.x), "f"(v.y), "f"(v.z), "f"(v.w)
                 : "memory");
}

// ---------------- K1: zero agg (= d_out) and degree counters ----------------
__global__ void init_kernel(float4* __restrict__ agg) {
    const int total4 = N_NODES * FEAT4;
    int stride = gridDim.x * blockDim.x;
    int i = blockIdx.x * blockDim.x + threadIdx.x;
    if (i < N_NODES) { g_deg_out[i] = 0; g_deg_in[i] = 0; }
    for (int j = i; j < total4; j += stride)
        agg[j] = make_float4(0.f, 0.f, 0.f, 0.f);
}

// ---------------- K2: degree counting ----------------
__global__ void degree_kernel(const int* __restrict__ src,
                              const int* __restrict__ dst) {
    int e = blockIdx.x * blockDim.x + threadIdx.x;
    if (e < N_EDGES) {
        atomicAdd(&g_deg_out[src[e]], 1);
        atomicAdd(&g_deg_in[dst[e]], 1);
    }
}

// ---------------- K3: per-node rsqrt coefficients ----------------
__global__ void rs_kernel() {
    int i = blockIdx.x * blockDim.x + threadIdx.x;
    if (i < N_NODES) {
        g_rs_out[i] = rsqrtf(fmaxf((float)g_deg_out[i], 1.0f));
        g_rs_in[i]  = rsqrtf(fmaxf((float)g_deg_in[i], 1.0f));
    }
}

// ---------------- K4: edge scatter (one warp per edge) ----------------
// agg[dst] += rs_out[src] * x[src]   (rs_in applied later, in the GEMM A load)
__global__ void __launch_bounds__(256) scatter_kernel(
    const float4* __restrict__ x,
    const int* __restrict__ src,
    const int* __restrict__ dst,
    float4* __restrict__ agg)
{
    int warp = (blockIdx.x * blockDim.x + threadIdx.x) >> 5;
    int lane = threadIdx.x & 31;
    if (warp >= N_EDGES) return;

    int s = __ldg(&src[warp]);
    int d = __ldg(&dst[warp]);
    float c = __ldg(&g_rs_out[s]);

    const float4* xs = x   + (size_t)s * FEAT4;
    float4*       ad = agg + (size_t)d * FEAT4;

    #pragma unroll
    for (int j = 0; j < 2; j++) {
        float4 v = __ldg(&xs[lane + 32 * j]);
        v.x *= c; v.y *= c; v.z *= c; v.w *= c;
        red_add_v4(&ad[lane + 32 * j], v);
    }
}

// ---------------- K5: fused GEMM + bias + ReLU + row L2-normalize ----------
// In-place: reads agg rows from `io`, writes normalized output to `io`.
// Tile: BM=64, BN=256 (full row), BK=16. 256 threads: tx=lane (N dir, 8 cols
// strided by 32), ty=warp (M dir, 8 rows). Each warp owns 8 complete rows ->
// epilogue row-reduction is a pure shfl butterfly.
#define BM 64
#define BK 16

__global__ void __launch_bounds__(256) gemm_kernel(
    float* __restrict__ io,          // agg in, normalized h out (in place)
    const float* __restrict__ Wm,    // [256,256] row-major
    const float* __restrict__ bias)
{
    __shared__ float As[BK][BM];        // A^T tile: As[k][row]
    __shared__ float Bs[BK][FEAT];      // B tile:  Bs[k][col]

    const int tid = threadIdx.x;
    const int tx = tid & 31;            // lane -> N direction
    const int ty = tid >> 5;            // warp -> M direction
    const int row0 = blockIdx.x * BM;

    float acc[8][8];
    #pragma unroll
    for (int i = 0; i < 8; i++)
        #pragma unroll
        for (int j = 0; j < 8; j++) acc[i][j] = 0.f;

    // A-load mapping: thread -> (row = tid/4, k4 = tid%4), one float4 each
    const int a_row = tid >> 2;
    const int a_k4  = (tid & 3) * 4;
    const int grow_a = row0 + a_row;
    const float rsin = (grow_a < N_NODES) ? g_rs_in[grow_a] : 0.f;
    const float4* a_src = (const float4*)(io + (size_t)grow_a * FEAT);

    for (int k0 = 0; k0 < FEAT; k0 += BK) {
        // load A tile (scaled by rs_in), transposed into As[k][row]
        float4 av = make_float4(0.f, 0.f, 0.f, 0.f);
        if (grow_a < N_NODES)
            av = __ldg(&a_src[(k0 + a_k4) >> 2]);
        As[a_k4 + 0][a_row] = av.x * rsin;
        As[a_k4 + 1][a_row] = av.y * rsin;
        As[a_k4 + 2][a_row] = av.z * rsin;
        As[a_k4 + 3][a_row] = av.w * rsin;

        // load B tile: 16x256 = 1024 float4, 4 per thread
        #pragma unroll
        for (int t = 0; t < 4; t++) {
            int slot = tid + t * 256;
            int bk = slot >> 6;          // 0..15
            int bn4 = slot & 63;         // float4 column
            float4 bv = __ldg((const float4*)(Wm + (size_t)(k0 + bk) * FEAT) + bn4);
            ((float4*)&Bs[bk][0])[bn4] = bv;
        }
        __syncthreads();

        #pragma unroll
        for (int k = 0; k < BK; k++) {
            float a[8], bb[8];
            #pragma unroll
            for (int i = 0; i < 8; i++) a[i] = As[k][ty * 8 + i];
            #pragma unroll
            for (int j = 0; j < 8; j++) bb[j] = Bs[k][tx + 32 * j];
            #pragma unroll
            for (int i = 0; i < 8; i++)
                #pragma unroll
                for (int j = 0; j < 8; j++)
                    acc[i][j] = fmaf(a[i], bb[j], acc[i][j]);
        }
        __syncthreads();
    }

    // epilogue: bias + relu + row L2 normalize + store
    float bv[8];
    #pragma unroll
    for (int j = 0; j < 8; j++) bv[j] = __ldg(&bias[tx + 32 * j]);

    #pragma unroll
    for (int i = 0; i < 8; i++) {
        int grow = row0 + ty * 8 + i;
        float ss = 0.f;
        float v[8];
        #pragma unroll
        for (int j = 0; j < 8; j++) {
            v[j] = fmaxf(acc[i][j] + bv[j], 0.f);   // bias + relu
            ss = fmaf(v[j], v[j], ss);
        }
        // full-row sum of squares across the 32 lanes of this warp
        #pragma unroll
        for (int off = 16; off > 0; off >>= 1)
            ss += __shfl_xor_sync(0xFFFFFFFFu, ss, off);
        float scale = 1.0f / fmaxf(sqrtf(ss), 1e-12f);
        if (grow < N_NODES) {
            float* o = io + (size_t)grow * FEAT;
            #pragma unroll
            for (int j = 0; j < 8; j++)
                o[tx + 32 * j] = v[j] * scale;
        }
    }
}

// ---------------- launch ----------------
extern "C" void kernel_launch(void* const* d_in, const int* in_sizes, int n_in,
                              void* d_out, int out_size) {
    const float* x   = (const float*)d_in[0];
    const float* Wm  = (const float*)d_in[1];
    const float* bia = (const float*)d_in[2];
    const int*   src = (const int*)d_in[3];
    const int*   dst = (const int*)d_in[4];
    float* out = (float*)d_out;

    init_kernel<<<4096, 256>>>((float4*)out);
    degree_kernel<<<(N_EDGES + 255) / 256, 256>>>(src, dst);
    rs_kernel<<<(N_NODES + 255) / 256, 256>>>();
    scatter_kernel<<<N_EDGES / 8, 256>>>((const float4*)x, src, dst, (float4*)out);
    gemm_kernel<<<(N_NODES + BM - 1) / BM, 256>>>(out, Wm, bia);
}

// round 2
// speedup vs baseline: 1.6976x; 1.6976x over previous
#include <cuda_runtime.h>
#include <cuda_bf16.h>
#include <math.h>

#define N_NODES 100000
#define N_EDGES 3200000
#define FEAT 256
#define FEAT4 (FEAT / 4)

// ---------------- device scratch (allocation-free contract) ----------------
__device__ int   g_deg_out[N_NODES];
__device__ int   g_deg_in[N_NODES];
__device__ float g_rs_out[N_NODES];     // rsqrt(max(deg_out,1))
__device__ float g_rs_in[N_NODES];      // rsqrt(max(deg_in,1))
__device__ int   g_off[N_NODES + 1];    // CSR offsets by dst
__device__ int   g_cursor[N_NODES];     // fill cursors
__device__ int   g_esrc[N_EDGES];       // src node id per CSR slot

// ---------------- K1: zero counters ----------------
__global__ void init_kernel() {
    int i = blockIdx.x * blockDim.x + threadIdx.x;
    if (i < N_NODES) { g_deg_out[i] = 0; g_deg_in[i] = 0; g_cursor[i] = 0; }
}

// ---------------- K2: degree counting ----------------
__global__ void degree_kernel(const int* __restrict__ src,
                              const int* __restrict__ dst) {
    int e = blockIdx.x * blockDim.x + threadIdx.x;
    if (e < N_EDGES) {
        atomicAdd(&g_deg_out[src[e]], 1);
        atomicAdd(&g_deg_in[dst[e]], 1);
    }
}

// ---------------- K3: per-node rsqrt coefficients ----------------
__global__ void rs_kernel() {
    int i = blockIdx.x * blockDim.x + threadIdx.x;
    if (i < N_NODES) {
        g_rs_out[i] = rsqrtf(fmaxf((float)g_deg_out[i], 1.0f));
        g_rs_in[i]  = rsqrtf(fmaxf((float)g_deg_in[i], 1.0f));
    }
}

// ---------------- K4: single-block exclusive scan of deg_in -> g_off ------
#define SCAN_T 1024
__global__ void __launch_bounds__(SCAN_T) scan_kernel() {
    __shared__ int part[SCAN_T];
    const int tid = threadIdx.x;
    const int chunk = (N_NODES + SCAN_T - 1) / SCAN_T;   // 98
    const int b = tid * chunk;
    const int e = min(b + chunk, N_NODES);

    int s = 0;
    for (int i = b; i < e; i++) s += g_deg_in[i];
    part[tid] = s;
    __syncthreads();

    // inclusive Hillis-Steele scan over 1024 partials
    int v = s;
    #pragma unroll
    for (int off = 1; off < SCAN_T; off <<= 1) {
        int t = (tid >= off) ? part[tid - off] : 0;
        __syncthreads();
        v = part[tid] + t;
        part[tid] = v;
        __syncthreads();
    }

    int run = v - s;   // exclusive prefix of this thread's chunk
    for (int i = b; i < e; i++) { g_off[i] = run; run += g_deg_in[i]; }
    if (tid == SCAN_T - 1) g_off[N_NODES] = part[SCAN_T - 1];
}

// ---------------- K5: CSR fill (counting-sort placement) ----------------
__global__ void fill_kernel(const int* __restrict__ src,
                            const int* __restrict__ dst) {
    int e = blockIdx.x * blockDim.x + threadIdx.x;
    if (e < N_EDGES) {
        int d = dst[e];
        int p = g_off[d] + atomicAdd(&g_cursor[d], 1);
        g_esrc[p] = src[e];
    }
}

// ---------------- K6: per-dst warp gather-accumulate ----------------
// io[d] = rs_in[d] * sum_{e in edges(d)} rs_out[src_e] * x[src_e]
// One warp per dst. 256 floats = 2 float4 per lane held in registers;
// single streaming store per row, no atomics.
__global__ void __launch_bounds__(256) gather_kernel(
    const float4* __restrict__ x,
    float4* __restrict__ io)
{
    int d = (blockIdx.x * blockDim.x + threadIdx.x) >> 5;
    int lane = threadIdx.x & 31;
    if (d >= N_NODES) return;

    const int beg = g_off[d];
    const int end = g_off[d + 1];

    float4 a0 = make_float4(0.f, 0.f, 0.f, 0.f);
    float4 a1 = make_float4(0.f, 0.f, 0.f, 0.f);

    int e = beg;
    // 4-edge unrolled main loop: 8 independent 128B loads in flight
    for (; e + 4 <= end; e += 4) {
        int   s0 = __ldg(&g_esrc[e + 0]);
        int   s1 = __ldg(&g_esrc[e + 1]);
        int   s2 = __ldg(&g_esrc[e + 2]);
        int   s3 = __ldg(&g_esrc[e + 3]);
        float c0 = __ldg(&g_rs_out[s0]);
        float c1 = __ldg(&g_rs_out[s1]);
        float c2 = __ldg(&g_rs_out[s2]);
        float c3 = __ldg(&g_rs_out[s3]);
        const float4* p0 = x + (size_t)s0 * FEAT4;
        const float4* p1 = x + (size_t)s1 * FEAT4;
        const float4* p2 = x + (size_t)s2 * FEAT4;
        const float4* p3 = x + (size_t)s3 * FEAT4;
        float4 u0 = __ldg(&p0[lane]);      float4 w0 = __ldg(&p0[lane + 32]);
        float4 u1 = __ldg(&p1[lane]);      float4 w1 = __ldg(&p1[lane + 32]);
        float4 u2 = __ldg(&p2[lane]);      float4 w2 = __ldg(&p2[lane + 32]);
        float4 u3 = __ldg(&p3[lane]);      float4 w3 = __ldg(&p3[lane + 32]);
        a0.x = fmaf(c0, u0.x, a0.x); a0.y = fmaf(c0, u0.y, a0.y);
        a0.z = fmaf(c0, u0.z, a0.z); a0.w = fmaf(c0, u0.w, a0.w);
        a1.x = fmaf(c0, w0.x, a1.x); a1.y = fmaf(c0, w0.y, a1.y);
        a1.z = fmaf(c0, w0.z, a1.z); a1.w = fmaf(c0, w0.w, a1.w);
        a0.x = fmaf(c1, u1.x, a0.x); a0.y = fmaf(c1, u1.y, a0.y);
        a0.z = fmaf(c1, u1.z, a0.z); a0.w = fmaf(c1, u1.w, a0.w);
        a1.x = fmaf(c1, w1.x, a1.x); a1.y = fmaf(c1, w1.y, a1.y);
        a1.z = fmaf(c1, w1.z, a1.z); a1.w = fmaf(c1, w1.w, a1.w);
        a0.x = fmaf(c2, u2.x, a0.x); a0.y = fmaf(c2, u2.y, a0.y);
        a0.z = fmaf(c2, u2.z, a0.z); a0.w = fmaf(c2, u2.w, a0.w);
        a1.x = fmaf(c2, w2.x, a1.x); a1.y = fmaf(c2, w2.y, a1.y);
        a1.z = fmaf(c2, w2.z, a1.z); a1.w = fmaf(c2, w2.w, a1.w);
        a0.x = fmaf(c3, u3.x, a0.x); a0.y = fmaf(c3, u3.y, a0.y);
        a0.z = fmaf(c3, u3.z, a0.z); a0.w = fmaf(c3, u3.w, a0.w);
        a1.x = fmaf(c3, w3.x, a1.x); a1.y = fmaf(c3, w3.y, a1.y);
        a1.z = fmaf(c3, w3.z, a1.z); a1.w = fmaf(c3, w3.w, a1.w);
    }
    for (; e < end; e++) {
        int   s = __ldg(&g_esrc[e]);
        float c = __ldg(&g_rs_out[s]);
        const float4* p = x + (size_t)s * FEAT4;
        float4 u = __ldg(&p[lane]);
        float4 w = __ldg(&p[lane + 32]);
        a0.x = fmaf(c, u.x, a0.x); a0.y = fmaf(c, u.y, a0.y);
        a0.z = fmaf(c, u.z, a0.z); a0.w = fmaf(c, u.w, a0.w);
        a1.x = fmaf(c, w.x, a1.x); a1.y = fmaf(c, w.y, a1.y);
        a1.z = fmaf(c, w.z, a1.z); a1.w = fmaf(c, w.w, a1.w);
    }

    const float ri = g_rs_in[d];
    a0.x *= ri; a0.y *= ri; a0.z *= ri; a0.w *= ri;
    a1.x *= ri; a1.y *= ri; a1.z *= ri; a1.w *= ri;
    float4* o = io + (size_t)d * FEAT4;
    o[lane]      = a0;
    o[lane + 32] = a1;
}

// ---------------- K7: fused GEMM + bias + ReLU + row L2-normalize ----------
// In-place on io. BM=64, BN=256(full row), BK=16. tx=lane(N), ty=warp(M).
#define BM 64
#define BK 16

__global__ void __launch_bounds__(256) gemm_kernel(
    float* __restrict__ io,
    const float* __restrict__ Wm,
    const float* __restrict__ bias)
{
    __shared__ float As[BK][BM];
    __shared__ float Bs[BK][FEAT];

    const int tid = threadIdx.x;
    const int tx = tid & 31;
    const int ty = tid >> 5;
    const int row0 = blockIdx.x * BM;

    float acc[8][8];
    #pragma unroll
    for (int i = 0; i < 8; i++)
        #pragma unroll
        for (int j = 0; j < 8; j++) acc[i][j] = 0.f;

    const int a_row = tid >> 2;
    const int a_k4  = (tid & 3) * 4;
    const int grow_a = row0 + a_row;
    const float4* a_src = (const float4*)(io + (size_t)grow_a * FEAT);

    for (int k0 = 0; k0 < FEAT; k0 += BK) {
        float4 av = make_float4(0.f, 0.f, 0.f, 0.f);
        if (grow_a < N_NODES)
            av = __ldg(&a_src[(k0 + a_k4) >> 2]);
        As[a_k4 + 0][a_row] = av.x;
        As[a_k4 + 1][a_row] = av.y;
        As[a_k4 + 2][a_row] = av.z;
        As[a_k4 + 3][a_row] = av.w;

        #pragma unroll
        for (int t = 0; t < 4; t++) {
            int slot = tid + t * 256;
            int bk = slot >> 6;
            int bn4 = slot & 63;
            float4 bv = __ldg((const float4*)(Wm + (size_t)(k0 + bk) * FEAT) + bn4);
            ((float4*)&Bs[bk][0])[bn4] = bv;
        }
        __syncthreads();

        #pragma unroll
        for (int k = 0; k < BK; k++) {
            float a[8], bb[8];
            #pragma unroll
            for (int i = 0; i < 8; i++) a[i] = As[k][ty * 8 + i];
            #pragma unroll
            for (int j = 0; j < 8; j++) bb[j] = Bs[k][tx + 32 * j];
            #pragma unroll
            for (int i = 0; i < 8; i++)
                #pragma unroll
                for (int j = 0; j < 8; j++)
                    acc[i][j] = fmaf(a[i], bb[j], acc[i][j]);
        }
        __syncthreads();
    }

    float bv[8];
    #pragma unroll
    for (int j = 0; j < 8; j++) bv[j] = __ldg(&bias[tx + 32 * j]);

    #pragma unroll
    for (int i = 0; i < 8; i++) {
        int grow = row0 + ty * 8 + i;
        float ss = 0.f;
        float v[8];
        #pragma unroll
        for (int j = 0; j < 8; j++) {
            v[j] = fmaxf(acc[i][j] + bv[j], 0.f);
            ss = fmaf(v[j], v[j], ss);
        }
        #pragma unroll
        for (int off = 16; off > 0; off >>= 1)
            ss += __shfl_xor_sync(0xFFFFFFFFu, ss, off);
        float scale = 1.0f / fmaxf(sqrtf(ss), 1e-12f);
        if (grow < N_NODES) {
            float* o = io + (size_t)grow * FEAT;
            #pragma unroll
            for (int j = 0; j < 8; j++)
                o[tx + 32 * j] = v[j] * scale;
        }
    }
}

// ---------------- launch ----------------
extern "C" void kernel_launch(void* const* d_in, const int* in_sizes, int n_in,
                              void* d_out, int out_size) {
    const float* x   = (const float*)d_in[0];
    const float* Wm  = (const float*)d_in[1];
    const float* bia = (const float*)d_in[2];
    const int*   src = (const int*)d_in[3];
    const int*   dst = (const int*)d_in[4];
    float* out = (float*)d_out;

    init_kernel<<<(N_NODES + 255) / 256, 256>>>();
    degree_kernel<<<(N_EDGES + 255) / 256, 256>>>(src, dst);
    rs_kernel<<<(N_NODES + 255) / 256, 256>>>();
    scan_kernel<<<1, SCAN_T>>>();
    fill_kernel<<<(N_EDGES + 255) / 256, 256>>>(src, dst);
    gather_kernel<<<(N_NODES * 32 + 255) / 256, 256>>>((const float4*)x, (float4*)out);
    gemm_kernel<<<(N_NODES + BM - 1) / BM, 256>>>(out, Wm, bia);
}